// round 14
// baseline (speedup 1.0000x reference)
#include <cuda_runtime.h>
#include <cuda_fp16.h>

#define NN 100000
#define NE 3200000
#define BN_EPS 1e-5f
#define NSCAN 98   // ceil((NN+1)/1024)
#define SCAN_FLAG 0x40000000

// ---------------- scratch (static device buffers) ---------------------------
__device__ float4 g_a[NN * 16];     // MLP output pre-BN (post relu2) [N,64] fp32
__device__ __half g_ah[NN * 64];    // post-BN+ReLU activations, fp16
__device__ int   g_deg[NN];         // zeroed at end of scanAC (deferred, deterministic)
__device__ int   g_rowstart[NN + 1];
__device__ int   g_cursor[NN];
__device__ int   g_src_sorted[NE];  // src index per edge, CSR order (layers 1-2)
__device__ float2 g_ex[NE];         // {x0,x1}[src] per edge, CSR order (layer 0)
__device__ unsigned char g_el[NE];  // label[src] per edge, CSR order (layer 0)
__device__ int   g_blocksums[NSCAN];
__device__ float g_stats[3 * 128];  // per layer: [0..63]=sum, [64..127]=sumsq

__device__ __forceinline__ float bnr(float v, float sc, float sh) {
    return fmaxf(fmaf(v, sc, sh), 0.0f);
}

// ---------------- packed f32x2 helpers (Blackwell FFMA2 path) ---------------
__device__ __forceinline__ unsigned long long packf2(float a, float b) {
    unsigned long long r;
    asm("mov.b64 %0, {%1, %2};" : "=l"(r) : "f"(a), "f"(b));
    return r;
}
__device__ __forceinline__ unsigned long long fma2(unsigned long long a,
                                                   unsigned long long b,
                                                   unsigned long long c) {
    unsigned long long d;
    asm("fma.rn.f32x2 %0, %1, %2, %3;" : "=l"(d) : "l"(a), "l"(b), "l"(c));
    return d;
}
__device__ __forceinline__ float2 unpackf2(unsigned long long v) {
    float2 r;
    asm("mov.b64 {%0, %1}, %2;" : "=f"(r.x), "=f"(r.y) : "l"(v));
    return r;
}

// ---------------- launch 0: zero stats/blocksums + histogram ----------------
// g_deg arrives already zeroed (module init on call 1; scanAC re-zeroes after).
__global__ void k_embedhist(const int4* __restrict__ dst4) {
    int n = blockIdx.x * blockDim.x + threadIdx.x;
    if (n < 3 * 128) g_stats[n] = 0.0f;
    if (n < NSCAN) g_blocksums[n] = 0;
    if (n < NE / 4) {
        int4 d = dst4[n];
        atomicAdd(&g_deg[d.x], 1);
        atomicAdd(&g_deg[d.y], 1);
        atomicAdd(&g_deg[d.z], 1);
        atomicAdd(&g_deg[d.w], 1);
    }
}

// ---------------- launch 1: single-kernel scan (parallel lookback) ----------
__global__ void k_scanAC() {
    __shared__ int sm[1024];
    __shared__ int boff;
    int t = threadIdx.x;
    int b = blockIdx.x;
    int i = b * 1024 + t;
    int v = (i < NN) ? g_deg[i] : 0;
    sm[t] = v;
    if (t == 0) boff = 0;
    __syncthreads();
    for (int off = 1; off < 1024; off <<= 1) {
        int add = (t >= off) ? sm[t - off] : 0;
        __syncthreads();
        sm[t] += add;
        __syncthreads();
    }
    if (t == 1023) atomicExch(&g_blocksums[b], sm[1023] | SCAN_FLAG);
    if (t < b) {
        int val;
        do { val = atomicAdd(&g_blocksums[t], 0); } while (!(val & SCAN_FLAG));
        atomicAdd(&boff, val & ~SCAN_FLAG);
    }
    __syncthreads();
    int excl = boff + sm[t] - v;
    if (i <= NN) g_rowstart[i] = excl;
    if (i < NN) {
        g_cursor[i] = excl;
        g_deg[i] = 0;           // deferred zero for next call's histogram
    }
}

// ---------------- launch 2: scatter (counting sort + payload sort) ----------
// Writes per edge: src index (layers 1-2) + layer-0 payload {x0,x1,label}
// in CSR order. Random loads of x/lab are latency-hidden by 3.2M threads.
__global__ void k_scatter(const int* __restrict__ src, const int* __restrict__ dst,
                          const float* __restrict__ x, const int* __restrict__ lab) {
    int e = blockIdx.x * blockDim.x + threadIdx.x;
    if (e >= NE) return;
    int s = src[e];
    int p = atomicAdd(&g_cursor[dst[e]], 1);
    g_src_sorted[p] = s;
    g_ex[p] = make_float2(x[2 * s], x[2 * s + 1]);
    g_el[p] = (unsigned char)lab[s];
}

// ---------------- launch 3 (PROFILED): fused layer-0 agg + MLP --------------
// Phase A: ALL 256 threads gather, 8 thr/node, SEQUENTIAL payload reads
//          (g_ex float2 + g_el u8, CSR order) + smem emb table (32x8 fp32).
//          Same register/summation structure as R13 -> bit-identical results.
// Phase B: FFMA2 MLP (DIN=10), unchanged.
#define SPN 89   // sP node stride (floats): odd vs 32 banks -> conflict-free reduce
__global__ void __launch_bounds__(256) k_aggmlp0x(const float* __restrict__ W1,
                                                  const float* __restrict__ b1,
                                                  const float* __restrict__ W2,
                                                  const float* __restrict__ b2,
                                                  const float* __restrict__ eps_ptr,
                                                  const float* __restrict__ emb,
                                                  const float* __restrict__ x,
                                                  const int* __restrict__ lab) {
    __shared__ float sW1[10 * 64];
    __shared__ float sW2[64 * 64];
    __shared__ float semb[32 * 8];
    __shared__ float sP[32 * SPN];
    __shared__ float sA[10 * 36];
    __shared__ float sB[64 * 36];
    __shared__ float sred[256];
    __shared__ float qred[256];

    int t = threadIdx.x;
    int node0 = blockIdx.x * 32;

    for (int i = t; i < 10 * 16; i += 256)
        ((float4*)sW1)[i] = ((const float4*)W1)[i];
    for (int i = t; i < 64 * 16; i += 256)
        ((float4*)sW2)[i] = ((const float4*)W2)[i];
    semb[t] = emb[t];                 // 256 = 32x8 exactly
    __syncthreads();

    // ---- Phase A: gather (8 thr/node, sequential payload + smem emb) ----
    {
        int nloc = t >> 3;
        int sub = t & 7;
        int node = node0 + nloc;
        int s = g_rowstart[node], e = g_rowstart[node + 1];
        float p0[10], p1[10];
#pragma unroll
        for (int k = 0; k < 10; k++) { p0[k] = 0.0f; p1[k] = 0.0f; }
        int j = s + sub;
        for (; j + 8 < e; j += 16) {
            float2 r0 = g_ex[j];
            float2 r1 = g_ex[j + 8];
            int c0 = g_el[j];
            int c1 = g_el[j + 8];
            {
                p0[0] += r0.x; p0[1] += r0.y;
                const float4* eb = (const float4*)&semb[c0 * 8];
                float4 e0 = eb[0], e1 = eb[1];
                p0[2] += e0.x; p0[3] += e0.y; p0[4] += e0.z; p0[5] += e0.w;
                p0[6] += e1.x; p0[7] += e1.y; p0[8] += e1.z; p0[9] += e1.w;
            }
            {
                p1[0] += r1.x; p1[1] += r1.y;
                const float4* eb = (const float4*)&semb[c1 * 8];
                float4 e0 = eb[0], e1 = eb[1];
                p1[2] += e0.x; p1[3] += e0.y; p1[4] += e0.z; p1[5] += e0.w;
                p1[6] += e1.x; p1[7] += e1.y; p1[8] += e1.z; p1[9] += e1.w;
            }
        }
        if (j < e) {
            float2 r0 = g_ex[j];
            int c0 = g_el[j];
            p0[0] += r0.x; p0[1] += r0.y;
            const float4* eb = (const float4*)&semb[c0 * 8];
            float4 e0 = eb[0], e1 = eb[1];
            p0[2] += e0.x; p0[3] += e0.y; p0[4] += e0.z; p0[5] += e0.w;
            p0[6] += e1.x; p0[7] += e1.y; p0[8] += e1.z; p0[9] += e1.w;
        }
        float* myP = &sP[nloc * SPN + sub * 10];
#pragma unroll
        for (int k = 0; k < 10; k++) myP[k] = p0[k] + p1[k];
    }
    __syncthreads();

    // ---- reduce 8 sub-partials -> sA[k][n], add (1+eps)*self ----
    {
        float c = 1.0f + *eps_ptr;
        for (int i = t; i < 320; i += 256) {
            int n = i & 31;
            int k = i >> 5;
            float ssum = 0.0f;
#pragma unroll
            for (int sub = 0; sub < 8; sub++) ssum += sP[n * SPN + sub * 10 + k];
            int node = node0 + n;
            float hk;
            if (k == 0)      hk = x[2 * node];
            else if (k == 1) hk = x[2 * node + 1];
            else             hk = semb[lab[node] * 8 + (k - 2)];
            sA[k * 36 + n] = fmaf(c, hk, ssum);
        }
    }
    __syncthreads();

    // ---- Phase B: 2-layer MLP (FFMA2, DIN=10) ----
    int f = t & 63;
    int g = t >> 6;

    unsigned long long a01, a23, a45, a67;
    {
        float bb = b1[f];
        unsigned long long bp = packf2(bb, bb);
        a01 = bp; a23 = bp; a45 = bp; a67 = bp;
    }
#pragma unroll
    for (int k = 0; k < 10; k++) {
        float w = sW1[k * 64 + f];
        unsigned long long ww = packf2(w, w);
        ulonglong2 p0 = *(const ulonglong2*)&sA[k * 36 + g * 8];
        ulonglong2 p1 = *(const ulonglong2*)&sA[k * 36 + g * 8 + 4];
        a01 = fma2(p0.x, ww, a01); a23 = fma2(p0.y, ww, a23);
        a45 = fma2(p1.x, ww, a45); a67 = fma2(p1.y, ww, a67);
    }
    {
        float2 v0 = unpackf2(a01), v1 = unpackf2(a23);
        float2 v2 = unpackf2(a45), v3 = unpackf2(a67);
        float4 y0 = make_float4(fmaxf(v0.x, 0.0f), fmaxf(v0.y, 0.0f),
                                fmaxf(v1.x, 0.0f), fmaxf(v1.y, 0.0f));
        float4 y1 = make_float4(fmaxf(v2.x, 0.0f), fmaxf(v2.y, 0.0f),
                                fmaxf(v3.x, 0.0f), fmaxf(v3.y, 0.0f));
        *(float4*)&sB[f * 36 + g * 8]     = y0;
        *(float4*)&sB[f * 36 + g * 8 + 4] = y1;
    }
    __syncthreads();

    {
        float bb = b2[f];
        unsigned long long bp = packf2(bb, bb);
        a01 = bp; a23 = bp; a45 = bp; a67 = bp;
    }
#pragma unroll
    for (int k = 0; k < 64; k++) {
        float w = sW2[k * 64 + f];
        unsigned long long ww = packf2(w, w);
        ulonglong2 p0 = *(const ulonglong2*)&sB[k * 36 + g * 8];
        ulonglong2 p1 = *(const ulonglong2*)&sB[k * 36 + g * 8 + 4];
        a01 = fma2(p0.x, ww, a01); a23 = fma2(p0.y, ww, a23);
        a45 = fma2(p1.x, ww, a45); a67 = fma2(p1.y, ww, a67);
    }

    float out8[8];
    {
        float2 v0 = unpackf2(a01), v1 = unpackf2(a23);
        float2 v2 = unpackf2(a45), v3 = unpackf2(a67);
        out8[0] = v0.x; out8[1] = v0.y; out8[2] = v1.x; out8[3] = v1.y;
        out8[4] = v2.x; out8[5] = v2.y; out8[6] = v3.x; out8[7] = v3.y;
    }

    float s = 0.0f, qq = 0.0f;
    float* ga = (float*)g_a;
#pragma unroll
    for (int i = 0; i < 8; i++) {
        float v = fmaxf(out8[i], 0.0f);
        ga[(node0 + g * 8 + i) * 64 + f] = v;
        s += v;
        qq += v * v;
    }
    sred[f * 4 + g] = s;
    qred[f * 4 + g] = qq;
    __syncthreads();
    if (t < 64) {
        float ss = sred[t * 4] + sred[t * 4 + 1] + sred[t * 4 + 2] + sred[t * 4 + 3];
        float q2 = qred[t * 4] + qred[t * 4 + 1] + qred[t * 4 + 2] + qred[t * 4 + 3];
        atomicAdd(&g_stats[0 * 128 + t], ss);
        atomicAdd(&g_stats[0 * 128 + 64 + t], q2);
    }
}
#undef SPN

// ---------------- BN apply + ReLU -> fp16: g_a (fp32) -> g_ah (half) --------
__global__ void __launch_bounds__(256) k_bnapply(int lidx,
                                                 const float* __restrict__ gamma,
                                                 const float* __restrict__ beta) {
    __shared__ float ssc[64], ssh[64];
    int t = threadIdx.x;
    if (t < 64) {
        float mu = g_stats[lidx * 128 + t] * (1.0f / NN);
        float var = g_stats[lidx * 128 + 64 + t] * (1.0f / NN) - mu * mu;
        float r = rsqrtf(var + BN_EPS) * gamma[t];
        ssc[t] = r;
        ssh[t] = beta[t] - mu * r;
    }
    __syncthreads();
    int p = blockIdx.x * 256 + t;              // pair index, NN*32 total
    if (p >= NN * 32) return;
    int f2 = p & 31;
    float2 v = ((const float2*)g_a)[p];
    float y0 = bnr(v.x, ssc[2 * f2], ssh[2 * f2]);
    float y1 = bnr(v.y, ssc[2 * f2 + 1], ssh[2 * f2 + 1]);
    ((__half2*)g_ah)[p] = __floats2half2_rn(y0, y1);
}

// per-value fp32 accumulate (R9 arithmetic — precision-frozen)
__device__ __forceinline__ void accum8(float* a, uint4 v) {
    const __half2* h = (const __half2*)&v;
#pragma unroll
    for (int i = 0; i < 4; i++) {
        float2 f = __half22float2(h[i]);
        a[2 * i]     += f.x;
        a[2 * i + 1] += f.y;
    }
}

// ---------------- FUSED layers 1,2: fp16 gather agg + 2-layer MLP (R9) ------
__global__ void __launch_bounds__(256) k_aggmlp(const float* __restrict__ W1,
                                                const float* __restrict__ b1,
                                                const float* __restrict__ W2,
                                                const float* __restrict__ b2,
                                                const float* __restrict__ eps_ptr,
                                                int lidx) {
    __shared__ float sW1[64 * 64];
    __shared__ float sW2[64 * 64];
    __shared__ float sAB[64 * 36];
    __shared__ float sred[256];
    __shared__ float qred[256];

    int t = threadIdx.x;
    int node0 = blockIdx.x * 32;

    for (int i = t; i < 64 * 16; i += 256)
        ((float4*)sW1)[i] = ((const float4*)W1)[i];
    for (int i = t; i < 64 * 16; i += 256)
        ((float4*)sW2)[i] = ((const float4*)W2)[i];

    // ---- Phase A: aggregation (8 thr/node, scalar idx, R9 exact) ----
    {
        int nloc = t >> 3;
        int q = t & 7;
        int node = node0 + nloc;
        const uint4* A = (const uint4*)g_ah;
        int s = g_rowstart[node], e = g_rowstart[node + 1];
        float a0[8] = {0, 0, 0, 0, 0, 0, 0, 0};
        float a1[8] = {0, 0, 0, 0, 0, 0, 0, 0};
        int j = s;
        for (; j + 3 < e; j += 4) {
            int s0 = g_src_sorted[j],     s1 = g_src_sorted[j + 1];
            int s2 = g_src_sorted[j + 2], s3 = g_src_sorted[j + 3];
            uint4 v0 = A[s0 * 8 + q], v1 = A[s1 * 8 + q];
            uint4 v2 = A[s2 * 8 + q], v3 = A[s3 * 8 + q];
            accum8(a0, v0); accum8(a1, v1); accum8(a0, v2); accum8(a1, v3);
        }
        for (; j < e; j++) accum8(a0, A[g_src_sorted[j] * 8 + q]);

        float c = 1.0f + *eps_ptr;
        uint4 w = A[node * 8 + q];
        const __half2* h = (const __half2*)&w;
#pragma unroll
        for (int i = 0; i < 4; i++) {
            float2 f = __half22float2(h[i]);
            float r0 = fmaf(c, f.x, a0[2 * i]     + a1[2 * i]);
            float r1 = fmaf(c, f.y, a0[2 * i + 1] + a1[2 * i + 1]);
            sAB[(q * 8 + 2 * i)     * 36 + nloc] = r0;
            sAB[(q * 8 + 2 * i + 1) * 36 + nloc] = r1;
        }
    }
    __syncthreads();

    // ---- Phase B: 2-layer MLP (FFMA2) ----
    int f = t & 63;
    int g = t >> 6;

    unsigned long long a01, a23, a45, a67;
    {
        float bb = b1[f];
        unsigned long long bp = packf2(bb, bb);
        a01 = bp; a23 = bp; a45 = bp; a67 = bp;
    }
#pragma unroll
    for (int k = 0; k < 64; k++) {
        float w = sW1[k * 64 + f];
        unsigned long long ww = packf2(w, w);
        ulonglong2 p0 = *(const ulonglong2*)&sAB[k * 36 + g * 8];
        ulonglong2 p1 = *(const ulonglong2*)&sAB[k * 36 + g * 8 + 4];
        a01 = fma2(p0.x, ww, a01); a23 = fma2(p0.y, ww, a23);
        a45 = fma2(p1.x, ww, a45); a67 = fma2(p1.y, ww, a67);
    }
    __syncthreads();
    {
        float2 v0 = unpackf2(a01), v1 = unpackf2(a23);
        float2 v2 = unpackf2(a45), v3 = unpackf2(a67);
        float4 y0 = make_float4(fmaxf(v0.x, 0.0f), fmaxf(v0.y, 0.0f),
                                fmaxf(v1.x, 0.0f), fmaxf(v1.y, 0.0f));
        float4 y1 = make_float4(fmaxf(v2.x, 0.0f), fmaxf(v2.y, 0.0f),
                                fmaxf(v3.x, 0.0f), fmaxf(v3.y, 0.0f));
        *(float4*)&sAB[f * 36 + g * 8]     = y0;
        *(float4*)&sAB[f * 36 + g * 8 + 4] = y1;
    }
    __syncthreads();

    {
        float bb = b2[f];
        unsigned long long bp = packf2(bb, bb);
        a01 = bp; a23 = bp; a45 = bp; a67 = bp;
    }
#pragma unroll
    for (int k = 0; k < 64; k++) {
        float w = sW2[k * 64 + f];
        unsigned long long ww = packf2(w, w);
        ulonglong2 p0 = *(const ulonglong2*)&sAB[k * 36 + g * 8];
        ulonglong2 p1 = *(const ulonglong2*)&sAB[k * 36 + g * 8 + 4];
        a01 = fma2(p0.x, ww, a01); a23 = fma2(p0.y, ww, a23);
        a45 = fma2(p1.x, ww, a45); a67 = fma2(p1.y, ww, a67);
    }

    float out8[8];
    {
        float2 v0 = unpackf2(a01), v1 = unpackf2(a23);
        float2 v2 = unpackf2(a45), v3 = unpackf2(a67);
        out8[0] = v0.x; out8[1] = v0.y; out8[2] = v1.x; out8[3] = v1.y;
        out8[4] = v2.x; out8[5] = v2.y; out8[6] = v3.x; out8[7] = v3.y;
    }

    float s = 0.0f, qq = 0.0f;
    float* ga = (float*)g_a;
#pragma unroll
    for (int i = 0; i < 8; i++) {
        float v = fmaxf(out8[i], 0.0f);
        ga[(node0 + g * 8 + i) * 64 + f] = v;
        s += v;
        qq += v * v;
    }
    sred[f * 4 + g] = s;
    qred[f * 4 + g] = qq;
    __syncthreads();
    if (t < 64) {
        float ss = sred[t * 4] + sred[t * 4 + 1] + sred[t * 4 + 2] + sred[t * 4 + 3];
        float q2 = qred[t * 4] + qred[t * 4 + 1] + qred[t * 4 + 2] + qred[t * 4 + 3];
        atomicAdd(&g_stats[lidx * 128 + t], ss);
        atomicAdd(&g_stats[lidx * 128 + 64 + t], q2);
    }
}

// ---------------- final: BN(layer2) + relu + linear head --------------------
__global__ void k_final(const float* __restrict__ gamma, const float* __restrict__ beta,
                        const float* __restrict__ Wf, const float* __restrict__ bf,
                        float* __restrict__ out) {
    int t = threadIdx.x;
    int lane = t & 31;
    int node = blockIdx.x * 8 + (t >> 5);
    const float* ga = (const float*)g_a;
    float total = 0.0f;
#pragma unroll
    for (int half = 0; half < 2; half++) {
        int f = lane + 32 * half;
        float mu = g_stats[2 * 128 + f] * (1.0f / NN);
        float var = g_stats[2 * 128 + 64 + f] * (1.0f / NN) - mu * mu;
        float v = (ga[node * 64 + f] - mu) * rsqrtf(var + BN_EPS) * gamma[f] + beta[f];
        total += fmaxf(v, 0.0f) * Wf[f];
    }
#pragma unroll
    for (int off = 16; off > 0; off >>= 1)
        total += __shfl_down_sync(0xffffffffu, total, off);
    if (lane == 0) out[node] = total + bf[0];
}

// ---------------- launch ----------------------------------------------------
extern "C" void kernel_launch(void* const* d_in, const int* in_sizes, int n_in,
                              void* d_out, int out_size) {
    const float* x       = (const float*)d_in[0];
    const int*   lab     = (const int*)d_in[1];
    const int*   ei      = (const int*)d_in[2];
    const float* emb     = (const float*)d_in[3];
    const float* W1_0    = (const float*)d_in[4];
    const float* b1_0    = (const float*)d_in[5];
    const float* W2_0    = (const float*)d_in[6];
    const float* b2_0    = (const float*)d_in[7];
    const float* eps_0   = (const float*)d_in[8];
    const float* gamma_0 = (const float*)d_in[9];
    const float* beta_0  = (const float*)d_in[10];
    const float* W1_s    = (const float*)d_in[11];
    const float* b1_s    = (const float*)d_in[12];
    const float* W2_s    = (const float*)d_in[13];
    const float* b2_s    = (const float*)d_in[14];
    const float* eps_s   = (const float*)d_in[15];
    const float* gamma_s = (const float*)d_in[16];
    const float* beta_s  = (const float*)d_in[17];
    const float* Wf      = (const float*)d_in[18];
    const float* bf      = (const float*)d_in[19];
    float* out = (float*)d_out;

    const int*  srcp = ei;
    const int*  dstp = ei + NE;
    const int4* dst4 = (const int4*)(ei + NE);

    // launch 0: zero stats/blocksums + histogram (deg pre-zeroed)
    k_embedhist<<<NE / 4 / 256, 256>>>(dst4);
    // launch 1: single-pass scan (+ deferred deg zero)
    k_scanAC<<<NSCAN, 1024>>>();
    // launch 2: scatter (index + layer-0 payload in CSR order)
    k_scatter<<<(NE + 255) / 256, 256>>>(srcp, dstp, x, lab);
    // launch 3 (profiled): fused layer-0 agg + MLP (sequential payload)
    k_aggmlp0x<<<NN / 32, 256>>>(W1_0, b1_0, W2_0, b2_0, eps_0, emb, x, lab);

    // layer 1: BN(l0) -> fp16, fused agg+MLP
    k_bnapply<<<(NN * 32 + 255) / 256, 256>>>(0, gamma_0, beta_0);
    k_aggmlp<<<NN / 32, 256>>>(W1_s + 0 * 4096, b1_s + 0 * 64,
                               W2_s + 0 * 4096, b2_s + 0 * 64, eps_s + 0, 1);

    // layer 2: BN(l1) -> fp16, fused agg+MLP
    k_bnapply<<<(NN * 32 + 255) / 256, 256>>>(1, gamma_s + 0 * 64, beta_s + 0 * 64);
    k_aggmlp<<<NN / 32, 256>>>(W1_s + 1 * 4096, b1_s + 1 * 64,
                               W2_s + 1 * 4096, b2_s + 1 * 64, eps_s + 1, 2);

    // final head (BN of layer 2 fused)
    k_final<<<NN / 8, 256>>>(gamma_s + 1 * 64, beta_s + 1 * 64, Wf, bf, out);
}

// round 15
// speedup vs baseline: 1.0918x; 1.0918x over previous
#include <cuda_runtime.h>
#include <cuda_fp16.h>

#define NN 100000
#define NE 3200000
#define BN_EPS 1e-5f
#define NSCAN 98   // ceil((NN+1)/1024)
#define SCAN_FLAG 0x40000000

// ---------------- scratch (static device buffers) ---------------------------
__device__ float4 g_p0[NN];         // packed layer-0 record {x0, x1, label, 0}
__device__ float4 g_a[NN * 16];     // MLP output pre-BN (post relu2) [N,64] fp32
__device__ __half g_ah[NN * 64];    // post-BN+ReLU activations, fp16
__device__ int   g_deg[NN];         // zeroed at end of scanAC (deferred, deterministic)
__device__ int   g_rowstart[NN + 1];
__device__ int   g_cursor[NN];
__device__ int   g_src_sorted[NE];
__device__ int   g_blocksums[NSCAN];
__device__ float g_stats[3 * 128];  // per layer: [0..63]=sum, [64..127]=sumsq

__device__ __forceinline__ float bnr(float v, float sc, float sh) {
    return fmaxf(fmaf(v, sc, sh), 0.0f);
}

// ---------------- packed f32x2 helpers (Blackwell FFMA2 path) ---------------
__device__ __forceinline__ unsigned long long packf2(float a, float b) {
    unsigned long long r;
    asm("mov.b64 %0, {%1, %2};" : "=l"(r) : "f"(a), "f"(b));
    return r;
}
__device__ __forceinline__ unsigned long long fma2(unsigned long long a,
                                                   unsigned long long b,
                                                   unsigned long long c) {
    unsigned long long d;
    asm("fma.rn.f32x2 %0, %1, %2, %3;" : "=l"(d) : "l"(a), "l"(b), "l"(c));
    return d;
}
__device__ __forceinline__ float2 unpackf2(unsigned long long v) {
    float2 r;
    asm("mov.b64 {%0, %1}, %2;" : "=f"(r.x), "=f"(r.y) : "l"(v));
    return r;
}

// ---------------- launch 0: embed-pack + zero stats/blocksums + histogram ---
// g_deg arrives already zeroed (module init on call 1; scanAC re-zeroes after).
__global__ void k_embedhist(const float* __restrict__ x, const int* __restrict__ lab,
                            const int4* __restrict__ dst4) {
    int n = blockIdx.x * blockDim.x + threadIdx.x;
    if (n < 3 * 128) g_stats[n] = 0.0f;
    if (n < NSCAN) g_blocksums[n] = 0;
    if (n < NN) {
        g_p0[n] = make_float4(x[2 * n], x[2 * n + 1],
                              __int_as_float(lab[n]), 0.0f);
    }
    if (n < NE / 4) {
        int4 d = dst4[n];
        atomicAdd(&g_deg[d.x], 1);
        atomicAdd(&g_deg[d.y], 1);
        atomicAdd(&g_deg[d.z], 1);
        atomicAdd(&g_deg[d.w], 1);
    }
}

// ---------------- launch 1: single-kernel scan (parallel lookback) ----------
__global__ void k_scanAC() {
    __shared__ int sm[1024];
    __shared__ int boff;
    int t = threadIdx.x;
    int b = blockIdx.x;
    int i = b * 1024 + t;
    int v = (i < NN) ? g_deg[i] : 0;
    sm[t] = v;
    if (t == 0) boff = 0;
    __syncthreads();
    for (int off = 1; off < 1024; off <<= 1) {
        int add = (t >= off) ? sm[t - off] : 0;
        __syncthreads();
        sm[t] += add;
        __syncthreads();
    }
    if (t == 1023) atomicExch(&g_blocksums[b], sm[1023] | SCAN_FLAG);
    if (t < b) {
        int val;
        do { val = atomicAdd(&g_blocksums[t], 0); } while (!(val & SCAN_FLAG));
        atomicAdd(&boff, val & ~SCAN_FLAG);
    }
    __syncthreads();
    int excl = boff + sm[t] - v;
    if (i <= NN) g_rowstart[i] = excl;
    if (i < NN) {
        g_cursor[i] = excl;
        g_deg[i] = 0;           // deferred zero for next call's histogram
    }
}

// ---------------- launch 2: scatter (counting-sort placement) ---------------
__global__ void k_scatter(const int* __restrict__ src, const int* __restrict__ dst) {
    int e = blockIdx.x * blockDim.x + threadIdx.x;
    if (e >= NE) return;
    int p = atomicAdd(&g_cursor[dst[e]], 1);
    g_src_sorted[p] = src[e];
}

// ---------------- launch 3 (PROFILED): fused layer-0 agg + MLP --------------
// Phase A: ALL 256 threads gather, 8 thr/node, 16 B packed record per edge;
//          emb table stored at STRIDE 12 floats (48 B, 16B-aligned) ->
//          LDS.128 conflict degree drops 8-way -> 4-way vs stride 8.
// Phase B: FFMA2 MLP (DIN=10), unchanged.
#define SPN 89   // sP node stride (floats): odd vs 32 banks -> conflict-free reduce
#define EMS 12   // semb row stride in floats (48 B)
__global__ void __launch_bounds__(256) k_aggmlp0e(const float* __restrict__ W1,
                                                  const float* __restrict__ b1,
                                                  const float* __restrict__ W2,
                                                  const float* __restrict__ b2,
                                                  const float* __restrict__ eps_ptr,
                                                  const float* __restrict__ emb) {
    __shared__ float sW1[10 * 64];
    __shared__ float sW2[64 * 64];
    __shared__ __align__(16) float semb[32 * EMS];
    __shared__ float sP[32 * SPN];
    __shared__ float sA[10 * 36];
    __shared__ float sB[64 * 36];
    __shared__ float sred[256];
    __shared__ float qred[256];

    int t = threadIdx.x;
    int node0 = blockIdx.x * 32;

    for (int i = t; i < 10 * 16; i += 256)
        ((float4*)sW1)[i] = ((const float4*)W1)[i];
    for (int i = t; i < 64 * 16; i += 256)
        ((float4*)sW2)[i] = ((const float4*)W2)[i];
    for (int i = t; i < 32 * EMS; i += 256) {
        int c = i / EMS, d = i % EMS;
        semb[i] = (d < 8) ? emb[c * 8 + d] : 0.0f;
    }
    __syncthreads();

    // ---- Phase A: gather (8 thr/node, packed records + stride-12 smem emb) -
    {
        int nloc = t >> 3;
        int sub = t & 7;
        int node = node0 + nloc;
        int s = g_rowstart[node], e = g_rowstart[node + 1];
        float p0[10], p1[10];
#pragma unroll
        for (int k = 0; k < 10; k++) { p0[k] = 0.0f; p1[k] = 0.0f; }
        int j = s + sub;
        for (; j + 8 < e; j += 16) {
            int i0 = g_src_sorted[j];
            int i1 = g_src_sorted[j + 8];
            float4 r0 = g_p0[i0];
            float4 r1 = g_p0[i1];
            {
                p0[0] += r0.x; p0[1] += r0.y;
                const float4* eb = (const float4*)&semb[__float_as_int(r0.z) * EMS];
                float4 e0 = eb[0], e1 = eb[1];
                p0[2] += e0.x; p0[3] += e0.y; p0[4] += e0.z; p0[5] += e0.w;
                p0[6] += e1.x; p0[7] += e1.y; p0[8] += e1.z; p0[9] += e1.w;
            }
            {
                p1[0] += r1.x; p1[1] += r1.y;
                const float4* eb = (const float4*)&semb[__float_as_int(r1.z) * EMS];
                float4 e0 = eb[0], e1 = eb[1];
                p1[2] += e0.x; p1[3] += e0.y; p1[4] += e0.z; p1[5] += e0.w;
                p1[6] += e1.x; p1[7] += e1.y; p1[8] += e1.z; p1[9] += e1.w;
            }
        }
        if (j < e) {
            float4 r0 = g_p0[g_src_sorted[j]];
            p0[0] += r0.x; p0[1] += r0.y;
            const float4* eb = (const float4*)&semb[__float_as_int(r0.z) * EMS];
            float4 e0 = eb[0], e1 = eb[1];
            p0[2] += e0.x; p0[3] += e0.y; p0[4] += e0.z; p0[5] += e0.w;
            p0[6] += e1.x; p0[7] += e1.y; p0[8] += e1.z; p0[9] += e1.w;
        }
        float* myP = &sP[nloc * SPN + sub * 10];
#pragma unroll
        for (int k = 0; k < 10; k++) myP[k] = p0[k] + p1[k];
    }
    __syncthreads();

    // ---- reduce 8 sub-partials -> sA[k][n], add (1+eps)*self ----
    {
        float c = 1.0f + *eps_ptr;
        for (int i = t; i < 320; i += 256) {
            int n = i & 31;
            int k = i >> 5;
            float ssum = 0.0f;
#pragma unroll
            for (int sub = 0; sub < 8; sub++) ssum += sP[n * SPN + sub * 10 + k];
            float4 rec = g_p0[node0 + n];
            float hk;
            if (k == 0)      hk = rec.x;
            else if (k == 1) hk = rec.y;
            else             hk = semb[__float_as_int(rec.z) * EMS + (k - 2)];
            sA[k * 36 + n] = fmaf(c, hk, ssum);
        }
    }
    __syncthreads();

    // ---- Phase B: 2-layer MLP (FFMA2, DIN=10) ----
    int f = t & 63;
    int g = t >> 6;

    unsigned long long a01, a23, a45, a67;
    {
        float bb = b1[f];
        unsigned long long bp = packf2(bb, bb);
        a01 = bp; a23 = bp; a45 = bp; a67 = bp;
    }
#pragma unroll
    for (int k = 0; k < 10; k++) {
        float w = sW1[k * 64 + f];
        unsigned long long ww = packf2(w, w);
        ulonglong2 p0 = *(const ulonglong2*)&sA[k * 36 + g * 8];
        ulonglong2 p1 = *(const ulonglong2*)&sA[k * 36 + g * 8 + 4];
        a01 = fma2(p0.x, ww, a01); a23 = fma2(p0.y, ww, a23);
        a45 = fma2(p1.x, ww, a45); a67 = fma2(p1.y, ww, a67);
    }
    {
        float2 v0 = unpackf2(a01), v1 = unpackf2(a23);
        float2 v2 = unpackf2(a45), v3 = unpackf2(a67);
        float4 y0 = make_float4(fmaxf(v0.x, 0.0f), fmaxf(v0.y, 0.0f),
                                fmaxf(v1.x, 0.0f), fmaxf(v1.y, 0.0f));
        float4 y1 = make_float4(fmaxf(v2.x, 0.0f), fmaxf(v2.y, 0.0f),
                                fmaxf(v3.x, 0.0f), fmaxf(v3.y, 0.0f));
        *(float4*)&sB[f * 36 + g * 8]     = y0;
        *(float4*)&sB[f * 36 + g * 8 + 4] = y1;
    }
    __syncthreads();

    {
        float bb = b2[f];
        unsigned long long bp = packf2(bb, bb);
        a01 = bp; a23 = bp; a45 = bp; a67 = bp;
    }
#pragma unroll
    for (int k = 0; k < 64; k++) {
        float w = sW2[k * 64 + f];
        unsigned long long ww = packf2(w, w);
        ulonglong2 p0 = *(const ulonglong2*)&sB[k * 36 + g * 8];
        ulonglong2 p1 = *(const ulonglong2*)&sB[k * 36 + g * 8 + 4];
        a01 = fma2(p0.x, ww, a01); a23 = fma2(p0.y, ww, a23);
        a45 = fma2(p1.x, ww, a45); a67 = fma2(p1.y, ww, a67);
    }

    float out8[8];
    {
        float2 v0 = unpackf2(a01), v1 = unpackf2(a23);
        float2 v2 = unpackf2(a45), v3 = unpackf2(a67);
        out8[0] = v0.x; out8[1] = v0.y; out8[2] = v1.x; out8[3] = v1.y;
        out8[4] = v2.x; out8[5] = v2.y; out8[6] = v3.x; out8[7] = v3.y;
    }

    float s = 0.0f, qq = 0.0f;
    float* ga = (float*)g_a;
#pragma unroll
    for (int i = 0; i < 8; i++) {
        float v = fmaxf(out8[i], 0.0f);
        ga[(node0 + g * 8 + i) * 64 + f] = v;
        s += v;
        qq += v * v;
    }
    sred[f * 4 + g] = s;
    qred[f * 4 + g] = qq;
    __syncthreads();
    if (t < 64) {
        float ss = sred[t * 4] + sred[t * 4 + 1] + sred[t * 4 + 2] + sred[t * 4 + 3];
        float q2 = qred[t * 4] + qred[t * 4 + 1] + qred[t * 4 + 2] + qred[t * 4 + 3];
        atomicAdd(&g_stats[0 * 128 + t], ss);
        atomicAdd(&g_stats[0 * 128 + 64 + t], q2);
    }
}
#undef SPN
#undef EMS

// ---------------- BN apply + ReLU -> fp16: g_a (fp32) -> g_ah (half) --------
__global__ void __launch_bounds__(256) k_bnapply(int lidx,
                                                 const float* __restrict__ gamma,
                                                 const float* __restrict__ beta) {
    __shared__ float ssc[64], ssh[64];
    int t = threadIdx.x;
    if (t < 64) {
        float mu = g_stats[lidx * 128 + t] * (1.0f / NN);
        float var = g_stats[lidx * 128 + 64 + t] * (1.0f / NN) - mu * mu;
        float r = rsqrtf(var + BN_EPS) * gamma[t];
        ssc[t] = r;
        ssh[t] = beta[t] - mu * r;
    }
    __syncthreads();
    int p = blockIdx.x * 256 + t;              // pair index, NN*32 total
    if (p >= NN * 32) return;
    int f2 = p & 31;
    float2 v = ((const float2*)g_a)[p];
    float y0 = bnr(v.x, ssc[2 * f2], ssh[2 * f2]);
    float y1 = bnr(v.y, ssc[2 * f2 + 1], ssh[2 * f2 + 1]);
    ((__half2*)g_ah)[p] = __floats2half2_rn(y0, y1);
}

// per-value fp32 accumulate (R9 arithmetic — precision-frozen)
__device__ __forceinline__ void accum8(float* a, uint4 v) {
    const __half2* h = (const __half2*)&v;
#pragma unroll
    for (int i = 0; i < 4; i++) {
        float2 f = __half22float2(h[i]);
        a[2 * i]     += f.x;
        a[2 * i + 1] += f.y;
    }
}

// ---------------- FUSED layers 1,2: fp16 gather agg + 2-layer MLP (R9) ------
__global__ void __launch_bounds__(256) k_aggmlp(const float* __restrict__ W1,
                                                const float* __restrict__ b1,
                                                const float* __restrict__ W2,
                                                const float* __restrict__ b2,
                                                const float* __restrict__ eps_ptr,
                                                int lidx) {
    __shared__ float sW1[64 * 64];
    __shared__ float sW2[64 * 64];
    __shared__ float sAB[64 * 36];
    __shared__ float sred[256];
    __shared__ float qred[256];

    int t = threadIdx.x;
    int node0 = blockIdx.x * 32;

    for (int i = t; i < 64 * 16; i += 256)
        ((float4*)sW1)[i] = ((const float4*)W1)[i];
    for (int i = t; i < 64 * 16; i += 256)
        ((float4*)sW2)[i] = ((const float4*)W2)[i];

    // ---- Phase A: aggregation (8 thr/node, scalar idx, R9 exact) ----
    {
        int nloc = t >> 3;
        int q = t & 7;
        int node = node0 + nloc;
        const uint4* A = (const uint4*)g_ah;
        int s = g_rowstart[node], e = g_rowstart[node + 1];
        float a0[8] = {0, 0, 0, 0, 0, 0, 0, 0};
        float a1[8] = {0, 0, 0, 0, 0, 0, 0, 0};
        int j = s;
        for (; j + 3 < e; j += 4) {
            int s0 = g_src_sorted[j],     s1 = g_src_sorted[j + 1];
            int s2 = g_src_sorted[j + 2], s3 = g_src_sorted[j + 3];
            uint4 v0 = A[s0 * 8 + q], v1 = A[s1 * 8 + q];
            uint4 v2 = A[s2 * 8 + q], v3 = A[s3 * 8 + q];
            accum8(a0, v0); accum8(a1, v1); accum8(a0, v2); accum8(a1, v3);
        }
        for (; j < e; j++) accum8(a0, A[g_src_sorted[j] * 8 + q]);

        float c = 1.0f + *eps_ptr;
        uint4 w = A[node * 8 + q];
        const __half2* h = (const __half2*)&w;
#pragma unroll
        for (int i = 0; i < 4; i++) {
            float2 f = __half22float2(h[i]);
            float r0 = fmaf(c, f.x, a0[2 * i]     + a1[2 * i]);
            float r1 = fmaf(c, f.y, a0[2 * i + 1] + a1[2 * i + 1]);
            sAB[(q * 8 + 2 * i)     * 36 + nloc] = r0;
            sAB[(q * 8 + 2 * i + 1) * 36 + nloc] = r1;
        }
    }
    __syncthreads();

    // ---- Phase B: 2-layer MLP (FFMA2) ----
    int f = t & 63;
    int g = t >> 6;

    unsigned long long a01, a23, a45, a67;
    {
        float bb = b1[f];
        unsigned long long bp = packf2(bb, bb);
        a01 = bp; a23 = bp; a45 = bp; a67 = bp;
    }
#pragma unroll
    for (int k = 0; k < 64; k++) {
        float w = sW1[k * 64 + f];
        unsigned long long ww = packf2(w, w);
        ulonglong2 p0 = *(const ulonglong2*)&sAB[k * 36 + g * 8];
        ulonglong2 p1 = *(const ulonglong2*)&sAB[k * 36 + g * 8 + 4];
        a01 = fma2(p0.x, ww, a01); a23 = fma2(p0.y, ww, a23);
        a45 = fma2(p1.x, ww, a45); a67 = fma2(p1.y, ww, a67);
    }
    __syncthreads();
    {
        float2 v0 = unpackf2(a01), v1 = unpackf2(a23);
        float2 v2 = unpackf2(a45), v3 = unpackf2(a67);
        float4 y0 = make_float4(fmaxf(v0.x, 0.0f), fmaxf(v0.y, 0.0f),
                                fmaxf(v1.x, 0.0f), fmaxf(v1.y, 0.0f));
        float4 y1 = make_float4(fmaxf(v2.x, 0.0f), fmaxf(v2.y, 0.0f),
                                fmaxf(v3.x, 0.0f), fmaxf(v3.y, 0.0f));
        *(float4*)&sAB[f * 36 + g * 8]     = y0;
        *(float4*)&sAB[f * 36 + g * 8 + 4] = y1;
    }
    __syncthreads();

    {
        float bb = b2[f];
        unsigned long long bp = packf2(bb, bb);
        a01 = bp; a23 = bp; a45 = bp; a67 = bp;
    }
#pragma unroll
    for (int k = 0; k < 64; k++) {
        float w = sW2[k * 64 + f];
        unsigned long long ww = packf2(w, w);
        ulonglong2 p0 = *(const ulonglong2*)&sAB[k * 36 + g * 8];
        ulonglong2 p1 = *(const ulonglong2*)&sAB[k * 36 + g * 8 + 4];
        a01 = fma2(p0.x, ww, a01); a23 = fma2(p0.y, ww, a23);
        a45 = fma2(p1.x, ww, a45); a67 = fma2(p1.y, ww, a67);
    }

    float out8[8];
    {
        float2 v0 = unpackf2(a01), v1 = unpackf2(a23);
        float2 v2 = unpackf2(a45), v3 = unpackf2(a67);
        out8[0] = v0.x; out8[1] = v0.y; out8[2] = v1.x; out8[3] = v1.y;
        out8[4] = v2.x; out8[5] = v2.y; out8[6] = v3.x; out8[7] = v3.y;
    }

    float s = 0.0f, qq = 0.0f;
    float* ga = (float*)g_a;
#pragma unroll
    for (int i = 0; i < 8; i++) {
        float v = fmaxf(out8[i], 0.0f);
        ga[(node0 + g * 8 + i) * 64 + f] = v;
        s += v;
        qq += v * v;
    }
    sred[f * 4 + g] = s;
    qred[f * 4 + g] = qq;
    __syncthreads();
    if (t < 64) {
        float ss = sred[t * 4] + sred[t * 4 + 1] + sred[t * 4 + 2] + sred[t * 4 + 3];
        float q2 = qred[t * 4] + qred[t * 4 + 1] + qred[t * 4 + 2] + qred[t * 4 + 3];
        atomicAdd(&g_stats[lidx * 128 + t], ss);
        atomicAdd(&g_stats[lidx * 128 + 64 + t], q2);
    }
}

// ---------------- final: BN(layer2) + relu + linear head --------------------
__global__ void k_final(const float* __restrict__ gamma, const float* __restrict__ beta,
                        const float* __restrict__ Wf, const float* __restrict__ bf,
                        float* __restrict__ out) {
    int t = threadIdx.x;
    int lane = t & 31;
    int node = blockIdx.x * 8 + (t >> 5);
    const float* ga = (const float*)g_a;
    float total = 0.0f;
#pragma unroll
    for (int half = 0; half < 2; half++) {
        int f = lane + 32 * half;
        float mu = g_stats[2 * 128 + f] * (1.0f / NN);
        float var = g_stats[2 * 128 + 64 + f] * (1.0f / NN) - mu * mu;
        float v = (ga[node * 64 + f] - mu) * rsqrtf(var + BN_EPS) * gamma[f] + beta[f];
        total += fmaxf(v, 0.0f) * Wf[f];
    }
#pragma unroll
    for (int off = 16; off > 0; off >>= 1)
        total += __shfl_down_sync(0xffffffffu, total, off);
    if (lane == 0) out[node] = total + bf[0];
}

// ---------------- launch ----------------------------------------------------
extern "C" void kernel_launch(void* const* d_in, const int* in_sizes, int n_in,
                              void* d_out, int out_size) {
    const float* x       = (const float*)d_in[0];
    const int*   lab     = (const int*)d_in[1];
    const int*   ei      = (const int*)d_in[2];
    const float* emb     = (const float*)d_in[3];
    const float* W1_0    = (const float*)d_in[4];
    const float* b1_0    = (const float*)d_in[5];
    const float* W2_0    = (const float*)d_in[6];
    const float* b2_0    = (const float*)d_in[7];
    const float* eps_0   = (const float*)d_in[8];
    const float* gamma_0 = (const float*)d_in[9];
    const float* beta_0  = (const float*)d_in[10];
    const float* W1_s    = (const float*)d_in[11];
    const float* b1_s    = (const float*)d_in[12];
    const float* W2_s    = (const float*)d_in[13];
    const float* b2_s    = (const float*)d_in[14];
    const float* eps_s   = (const float*)d_in[15];
    const float* gamma_s = (const float*)d_in[16];
    const float* beta_s  = (const float*)d_in[17];
    const float* Wf      = (const float*)d_in[18];
    const float* bf      = (const float*)d_in[19];
    float* out = (float*)d_out;

    const int*  srcp = ei;
    const int*  dstp = ei + NE;
    const int4* dst4 = (const int4*)(ei + NE);

    // launch 0: embed-pack + zero stats/blocksums + histogram (deg pre-zeroed)
    k_embedhist<<<NE / 4 / 256, 256>>>(x, lab, dst4);
    // launch 1: single-pass scan (+ deferred deg zero)
    k_scanAC<<<NSCAN, 1024>>>();
    // launch 2: scatter (index only — R13 form)
    k_scatter<<<(NE + 255) / 256, 256>>>(srcp, dstp);
    // launch 3 (profiled): fused layer-0 agg + MLP (stride-12 emb table)
    k_aggmlp0e<<<NN / 32, 256>>>(W1_0, b1_0, W2_0, b2_0, eps_0, emb);

    // layer 1: BN(l0) -> fp16, fused agg+MLP
    k_bnapply<<<(NN * 32 + 255) / 256, 256>>>(0, gamma_0, beta_0);
    k_aggmlp<<<NN / 32, 256>>>(W1_s + 0 * 4096, b1_s + 0 * 64,
                               W2_s + 0 * 4096, b2_s + 0 * 64, eps_s + 0, 1);

    // layer 2: BN(l1) -> fp16, fused agg+MLP
    k_bnapply<<<(NN * 32 + 255) / 256, 256>>>(1, gamma_s + 0 * 64, beta_s + 0 * 64);
    k_aggmlp<<<NN / 32, 256>>>(W1_s + 1 * 4096, b1_s + 1 * 64,
                               W2_s + 1 * 4096, b2_s + 1 * 64, eps_s + 1, 2);

    // final head (BN of layer 2 fused)
    k_final<<<NN / 8, 256>>>(gamma_s + 1 * 64, beta_s + 1 * 64, Wf, bf, out);
}

// round 16
// speedup vs baseline: 1.1893x; 1.0893x over previous
#include <cuda_runtime.h>
#include <cuda_fp16.h>

#define NN 100000
#define NE 3200000
#define BN_EPS 1e-5f
#define NSCAN 98   // ceil((NN+1)/1024)
#define SCAN_FLAG 0x40000000

// ---------------- scratch (static device buffers) ---------------------------
__device__ float4 g_p0[NN];         // packed layer-0 record {x0, x1, label, 0}
__device__ float4 g_a[NN * 16];     // MLP output pre-BN (post relu2) [N,64] fp32
__device__ __half g_ah[NN * 64];    // post-BN+ReLU activations, fp16
__device__ int   g_deg[NN];         // zeroed at end of scanAC (deferred, deterministic)
__device__ int   g_rowstart[NN + 1];
__device__ int   g_cursor[NN];
__device__ int   g_src_sorted[NE];
__device__ int   g_blocksums[NSCAN];
__device__ float g_stats[3 * 128];  // per layer: [0..63]=sum, [64..127]=sumsq

__device__ __forceinline__ float bnr(float v, float sc, float sh) {
    return fmaxf(fmaf(v, sc, sh), 0.0f);
}

// ---------------- packed f32x2 helpers (Blackwell FFMA2 path) ---------------
__device__ __forceinline__ unsigned long long packf2(float a, float b) {
    unsigned long long r;
    asm("mov.b64 %0, {%1, %2};" : "=l"(r) : "f"(a), "f"(b));
    return r;
}
__device__ __forceinline__ unsigned long long fma2(unsigned long long a,
                                                   unsigned long long b,
                                                   unsigned long long c) {
    unsigned long long d;
    asm("fma.rn.f32x2 %0, %1, %2, %3;" : "=l"(d) : "l"(a), "l"(b), "l"(c));
    return d;
}
__device__ __forceinline__ float2 unpackf2(unsigned long long v) {
    float2 r;
    asm("mov.b64 {%0, %1}, %2;" : "=f"(r.x), "=f"(r.y) : "l"(v));
    return r;
}

// ---------------- launch 0: embed-pack + zero stats/blocksums + histogram ---
// g_deg arrives already zeroed (module init on call 1; scanAC re-zeroes after).
__global__ void k_embedhist(const float* __restrict__ x, const int* __restrict__ lab,
                            const int4* __restrict__ dst4) {
    int n = blockIdx.x * blockDim.x + threadIdx.x;
    if (n < 3 * 128) g_stats[n] = 0.0f;
    if (n < NSCAN) g_blocksums[n] = 0;
    if (n < NN) {
        g_p0[n] = make_float4(x[2 * n], x[2 * n + 1],
                              __int_as_float(lab[n]), 0.0f);
    }
    if (n < NE / 4) {
        int4 d = dst4[n];
        atomicAdd(&g_deg[d.x], 1);
        atomicAdd(&g_deg[d.y], 1);
        atomicAdd(&g_deg[d.z], 1);
        atomicAdd(&g_deg[d.w], 1);
    }
}

// ---------------- launch 1: single-kernel scan (parallel lookback) ----------
__global__ void k_scanAC() {
    __shared__ int sm[1024];
    __shared__ int boff;
    int t = threadIdx.x;
    int b = blockIdx.x;
    int i = b * 1024 + t;
    int v = (i < NN) ? g_deg[i] : 0;
    sm[t] = v;
    if (t == 0) boff = 0;
    __syncthreads();
    for (int off = 1; off < 1024; off <<= 1) {
        int add = (t >= off) ? sm[t - off] : 0;
        __syncthreads();
        sm[t] += add;
        __syncthreads();
    }
    if (t == 1023) atomicExch(&g_blocksums[b], sm[1023] | SCAN_FLAG);
    if (t < b) {
        int val;
        do { val = atomicAdd(&g_blocksums[t], 0); } while (!(val & SCAN_FLAG));
        atomicAdd(&boff, val & ~SCAN_FLAG);
    }
    __syncthreads();
    int excl = boff + sm[t] - v;
    if (i <= NN) g_rowstart[i] = excl;
    if (i < NN) {
        g_cursor[i] = excl;
        g_deg[i] = 0;           // deferred zero for next call's histogram
    }
}

// ---------------- launch 2: scatter (counting-sort placement) ---------------
__global__ void k_scatter(const int* __restrict__ src, const int* __restrict__ dst) {
    int e = blockIdx.x * blockDim.x + threadIdx.x;
    if (e >= NE) return;
    int p = atomicAdd(&g_cursor[dst[e]], 1);
    g_src_sorted[p] = src[e];
}

// ---------------- launch 3 (PROFILED): fused layer-0 agg + MLP --------------
// Weights read directly from gmem (L1-resident, coalesced, shared across
// blocks) -> smem 45 -> 26 KB -> ~2x resident blocks for latency hiding.
#define SPN 89   // sP node stride (floats): odd vs 32 banks -> conflict-free reduce
#define EMS 12   // semb row stride in floats (48 B)
__global__ void __launch_bounds__(256) k_aggmlp0e(const float* __restrict__ W1,
                                                  const float* __restrict__ b1,
                                                  const float* __restrict__ W2,
                                                  const float* __restrict__ b2,
                                                  const float* __restrict__ eps_ptr,
                                                  const float* __restrict__ emb) {
    __shared__ __align__(16) float semb[32 * EMS];
    __shared__ float sP[32 * SPN];
    __shared__ float sA[10 * 36];
    __shared__ float sB[64 * 36];
    __shared__ float sred[256];
    __shared__ float qred[256];

    int t = threadIdx.x;
    int node0 = blockIdx.x * 32;

    for (int i = t; i < 32 * EMS; i += 256) {
        int c = i / EMS, d = i % EMS;
        semb[i] = (d < 8) ? emb[c * 8 + d] : 0.0f;
    }
    __syncthreads();

    // ---- Phase A: gather (8 thr/node, packed records + stride-12 smem emb) -
    {
        int nloc = t >> 3;
        int sub = t & 7;
        int node = node0 + nloc;
        int s = g_rowstart[node], e = g_rowstart[node + 1];
        float p0[10], p1[10];
#pragma unroll
        for (int k = 0; k < 10; k++) { p0[k] = 0.0f; p1[k] = 0.0f; }
        int j = s + sub;
        for (; j + 8 < e; j += 16) {
            int i0 = g_src_sorted[j];
            int i1 = g_src_sorted[j + 8];
            float4 r0 = g_p0[i0];
            float4 r1 = g_p0[i1];
            {
                p0[0] += r0.x; p0[1] += r0.y;
                const float4* eb = (const float4*)&semb[__float_as_int(r0.z) * EMS];
                float4 e0 = eb[0], e1 = eb[1];
                p0[2] += e0.x; p0[3] += e0.y; p0[4] += e0.z; p0[5] += e0.w;
                p0[6] += e1.x; p0[7] += e1.y; p0[8] += e1.z; p0[9] += e1.w;
            }
            {
                p1[0] += r1.x; p1[1] += r1.y;
                const float4* eb = (const float4*)&semb[__float_as_int(r1.z) * EMS];
                float4 e0 = eb[0], e1 = eb[1];
                p1[2] += e0.x; p1[3] += e0.y; p1[4] += e0.z; p1[5] += e0.w;
                p1[6] += e1.x; p1[7] += e1.y; p1[8] += e1.z; p1[9] += e1.w;
            }
        }
        if (j < e) {
            float4 r0 = g_p0[g_src_sorted[j]];
            p0[0] += r0.x; p0[1] += r0.y;
            const float4* eb = (const float4*)&semb[__float_as_int(r0.z) * EMS];
            float4 e0 = eb[0], e1 = eb[1];
            p0[2] += e0.x; p0[3] += e0.y; p0[4] += e0.z; p0[5] += e0.w;
            p0[6] += e1.x; p0[7] += e1.y; p0[8] += e1.z; p0[9] += e1.w;
        }
        float* myP = &sP[nloc * SPN + sub * 10];
#pragma unroll
        for (int k = 0; k < 10; k++) myP[k] = p0[k] + p1[k];
    }
    __syncthreads();

    // ---- reduce 8 sub-partials -> sA[k][n], add (1+eps)*self ----
    {
        float c = 1.0f + *eps_ptr;
        for (int i = t; i < 320; i += 256) {
            int n = i & 31;
            int k = i >> 5;
            float ssum = 0.0f;
#pragma unroll
            for (int sub = 0; sub < 8; sub++) ssum += sP[n * SPN + sub * 10 + k];
            float4 rec = g_p0[node0 + n];
            float hk;
            if (k == 0)      hk = rec.x;
            else if (k == 1) hk = rec.y;
            else             hk = semb[__float_as_int(rec.z) * EMS + (k - 2)];
            sA[k * 36 + n] = fmaf(c, hk, ssum);
        }
    }
    __syncthreads();

    // ---- Phase B: 2-layer MLP (FFMA2, DIN=10, weights from gmem) ----
    int f = t & 63;
    int g = t >> 6;

    unsigned long long a01, a23, a45, a67;
    {
        float bb = b1[f];
        unsigned long long bp = packf2(bb, bb);
        a01 = bp; a23 = bp; a45 = bp; a67 = bp;
    }
#pragma unroll
    for (int k = 0; k < 10; k++) {
        float w = __ldg(&W1[k * 64 + f]);
        unsigned long long ww = packf2(w, w);
        ulonglong2 p0 = *(const ulonglong2*)&sA[k * 36 + g * 8];
        ulonglong2 p1 = *(const ulonglong2*)&sA[k * 36 + g * 8 + 4];
        a01 = fma2(p0.x, ww, a01); a23 = fma2(p0.y, ww, a23);
        a45 = fma2(p1.x, ww, a45); a67 = fma2(p1.y, ww, a67);
    }
    {
        float2 v0 = unpackf2(a01), v1 = unpackf2(a23);
        float2 v2 = unpackf2(a45), v3 = unpackf2(a67);
        float4 y0 = make_float4(fmaxf(v0.x, 0.0f), fmaxf(v0.y, 0.0f),
                                fmaxf(v1.x, 0.0f), fmaxf(v1.y, 0.0f));
        float4 y1 = make_float4(fmaxf(v2.x, 0.0f), fmaxf(v2.y, 0.0f),
                                fmaxf(v3.x, 0.0f), fmaxf(v3.y, 0.0f));
        *(float4*)&sB[f * 36 + g * 8]     = y0;
        *(float4*)&sB[f * 36 + g * 8 + 4] = y1;
    }
    __syncthreads();

    {
        float bb = b2[f];
        unsigned long long bp = packf2(bb, bb);
        a01 = bp; a23 = bp; a45 = bp; a67 = bp;
    }
#pragma unroll
    for (int k = 0; k < 64; k++) {
        float w = __ldg(&W2[k * 64 + f]);
        unsigned long long ww = packf2(w, w);
        ulonglong2 p0 = *(const ulonglong2*)&sB[k * 36 + g * 8];
        ulonglong2 p1 = *(const ulonglong2*)&sB[k * 36 + g * 8 + 4];
        a01 = fma2(p0.x, ww, a01); a23 = fma2(p0.y, ww, a23);
        a45 = fma2(p1.x, ww, a45); a67 = fma2(p1.y, ww, a67);
    }

    float out8[8];
    {
        float2 v0 = unpackf2(a01), v1 = unpackf2(a23);
        float2 v2 = unpackf2(a45), v3 = unpackf2(a67);
        out8[0] = v0.x; out8[1] = v0.y; out8[2] = v1.x; out8[3] = v1.y;
        out8[4] = v2.x; out8[5] = v2.y; out8[6] = v3.x; out8[7] = v3.y;
    }

    float s = 0.0f, qq = 0.0f;
    float* ga = (float*)g_a;
#pragma unroll
    for (int i = 0; i < 8; i++) {
        float v = fmaxf(out8[i], 0.0f);
        ga[(node0 + g * 8 + i) * 64 + f] = v;
        s += v;
        qq += v * v;
    }
    sred[f * 4 + g] = s;
    qred[f * 4 + g] = qq;
    __syncthreads();
    if (t < 64) {
        float ss = sred[t * 4] + sred[t * 4 + 1] + sred[t * 4 + 2] + sred[t * 4 + 3];
        float q2 = qred[t * 4] + qred[t * 4 + 1] + qred[t * 4 + 2] + qred[t * 4 + 3];
        atomicAdd(&g_stats[0 * 128 + t], ss);
        atomicAdd(&g_stats[0 * 128 + 64 + t], q2);
    }
}
#undef SPN
#undef EMS

// ---------------- BN apply + ReLU -> fp16: g_a (fp32) -> g_ah (half) --------
__global__ void __launch_bounds__(256) k_bnapply(int lidx,
                                                 const float* __restrict__ gamma,
                                                 const float* __restrict__ beta) {
    __shared__ float ssc[64], ssh[64];
    int t = threadIdx.x;
    if (t < 64) {
        float mu = g_stats[lidx * 128 + t] * (1.0f / NN);
        float var = g_stats[lidx * 128 + 64 + t] * (1.0f / NN) - mu * mu;
        float r = rsqrtf(var + BN_EPS) * gamma[t];
        ssc[t] = r;
        ssh[t] = beta[t] - mu * r;
    }
    __syncthreads();
    int p = blockIdx.x * 256 + t;              // pair index, NN*32 total
    if (p >= NN * 32) return;
    int f2 = p & 31;
    float2 v = ((const float2*)g_a)[p];
    float y0 = bnr(v.x, ssc[2 * f2], ssh[2 * f2]);
    float y1 = bnr(v.y, ssc[2 * f2 + 1], ssh[2 * f2 + 1]);
    ((__half2*)g_ah)[p] = __floats2half2_rn(y0, y1);
}

// per-value fp32 accumulate (R9 arithmetic — precision-frozen)
__device__ __forceinline__ void accum8(float* a, uint4 v) {
    const __half2* h = (const __half2*)&v;
#pragma unroll
    for (int i = 0; i < 4; i++) {
        float2 f = __half22float2(h[i]);
        a[2 * i]     += f.x;
        a[2 * i + 1] += f.y;
    }
}

// ---------------- FUSED layers 1,2: fp16 gather agg + 2-layer MLP -----------
// Weights read directly from gmem -> smem 43 -> 11 KB -> ~2x resident blocks.
__global__ void __launch_bounds__(256) k_aggmlp(const float* __restrict__ W1,
                                                const float* __restrict__ b1,
                                                const float* __restrict__ W2,
                                                const float* __restrict__ b2,
                                                const float* __restrict__ eps_ptr,
                                                int lidx) {
    __shared__ float sAB[64 * 36];
    __shared__ float sred[256];
    __shared__ float qred[256];

    int t = threadIdx.x;
    int node0 = blockIdx.x * 32;

    // ---- Phase A: aggregation (8 thr/node, scalar idx, R9 exact) ----
    {
        int nloc = t >> 3;
        int q = t & 7;
        int node = node0 + nloc;
        const uint4* A = (const uint4*)g_ah;
        int s = g_rowstart[node], e = g_rowstart[node + 1];
        float a0[8] = {0, 0, 0, 0, 0, 0, 0, 0};
        float a1[8] = {0, 0, 0, 0, 0, 0, 0, 0};
        int j = s;
        for (; j + 3 < e; j += 4) {
            int s0 = g_src_sorted[j],     s1 = g_src_sorted[j + 1];
            int s2 = g_src_sorted[j + 2], s3 = g_src_sorted[j + 3];
            uint4 v0 = A[s0 * 8 + q], v1 = A[s1 * 8 + q];
            uint4 v2 = A[s2 * 8 + q], v3 = A[s3 * 8 + q];
            accum8(a0, v0); accum8(a1, v1); accum8(a0, v2); accum8(a1, v3);
        }
        for (; j < e; j++) accum8(a0, A[g_src_sorted[j] * 8 + q]);

        float c = 1.0f + *eps_ptr;
        uint4 w = A[node * 8 + q];
        const __half2* h = (const __half2*)&w;
#pragma unroll
        for (int i = 0; i < 4; i++) {
            float2 f = __half22float2(h[i]);
            float r0 = fmaf(c, f.x, a0[2 * i]     + a1[2 * i]);
            float r1 = fmaf(c, f.y, a0[2 * i + 1] + a1[2 * i + 1]);
            sAB[(q * 8 + 2 * i)     * 36 + nloc] = r0;
            sAB[(q * 8 + 2 * i + 1) * 36 + nloc] = r1;
        }
    }
    __syncthreads();

    // ---- Phase B: 2-layer MLP (FFMA2, weights from gmem) ----
    int f = t & 63;
    int g = t >> 6;

    unsigned long long a01, a23, a45, a67;
    {
        float bb = b1[f];
        unsigned long long bp = packf2(bb, bb);
        a01 = bp; a23 = bp; a45 = bp; a67 = bp;
    }
#pragma unroll
    for (int k = 0; k < 64; k++) {
        float w = __ldg(&W1[k * 64 + f]);
        unsigned long long ww = packf2(w, w);
        ulonglong2 p0 = *(const ulonglong2*)&sAB[k * 36 + g * 8];
        ulonglong2 p1 = *(const ulonglong2*)&sAB[k * 36 + g * 8 + 4];
        a01 = fma2(p0.x, ww, a01); a23 = fma2(p0.y, ww, a23);
        a45 = fma2(p1.x, ww, a45); a67 = fma2(p1.y, ww, a67);
    }
    __syncthreads();
    {
        float2 v0 = unpackf2(a01), v1 = unpackf2(a23);
        float2 v2 = unpackf2(a45), v3 = unpackf2(a67);
        float4 y0 = make_float4(fmaxf(v0.x, 0.0f), fmaxf(v0.y, 0.0f),
                                fmaxf(v1.x, 0.0f), fmaxf(v1.y, 0.0f));
        float4 y1 = make_float4(fmaxf(v2.x, 0.0f), fmaxf(v2.y, 0.0f),
                                fmaxf(v3.x, 0.0f), fmaxf(v3.y, 0.0f));
        *(float4*)&sAB[f * 36 + g * 8]     = y0;
        *(float4*)&sAB[f * 36 + g * 8 + 4] = y1;
    }
    __syncthreads();

    {
        float bb = b2[f];
        unsigned long long bp = packf2(bb, bb);
        a01 = bp; a23 = bp; a45 = bp; a67 = bp;
    }
#pragma unroll
    for (int k = 0; k < 64; k++) {
        float w = __ldg(&W2[k * 64 + f]);
        unsigned long long ww = packf2(w, w);
        ulonglong2 p0 = *(const ulonglong2*)&sAB[k * 36 + g * 8];
        ulonglong2 p1 = *(const ulonglong2*)&sAB[k * 36 + g * 8 + 4];
        a01 = fma2(p0.x, ww, a01); a23 = fma2(p0.y, ww, a23);
        a45 = fma2(p1.x, ww, a45); a67 = fma2(p1.y, ww, a67);
    }

    float out8[8];
    {
        float2 v0 = unpackf2(a01), v1 = unpackf2(a23);
        float2 v2 = unpackf2(a45), v3 = unpackf2(a67);
        out8[0] = v0.x; out8[1] = v0.y; out8[2] = v1.x; out8[3] = v1.y;
        out8[4] = v2.x; out8[5] = v2.y; out8[6] = v3.x; out8[7] = v3.y;
    }

    float s = 0.0f, qq = 0.0f;
    float* ga = (float*)g_a;
#pragma unroll
    for (int i = 0; i < 8; i++) {
        float v = fmaxf(out8[i], 0.0f);
        ga[(node0 + g * 8 + i) * 64 + f] = v;
        s += v;
        qq += v * v;
    }
    sred[f * 4 + g] = s;
    qred[f * 4 + g] = qq;
    __syncthreads();
    if (t < 64) {
        float ss = sred[t * 4] + sred[t * 4 + 1] + sred[t * 4 + 2] + sred[t * 4 + 3];
        float q2 = qred[t * 4] + qred[t * 4 + 1] + qred[t * 4 + 2] + qred[t * 4 + 3];
        atomicAdd(&g_stats[lidx * 128 + t], ss);
        atomicAdd(&g_stats[lidx * 128 + 64 + t], q2);
    }
}

// ---------------- final: BN(layer2) + relu + linear head --------------------
__global__ void k_final(const float* __restrict__ gamma, const float* __restrict__ beta,
                        const float* __restrict__ Wf, const float* __restrict__ bf,
                        float* __restrict__ out) {
    int t = threadIdx.x;
    int lane = t & 31;
    int node = blockIdx.x * 8 + (t >> 5);
    const float* ga = (const float*)g_a;
    float total = 0.0f;
#pragma unroll
    for (int half = 0; half < 2; half++) {
        int f = lane + 32 * half;
        float mu = g_stats[2 * 128 + f] * (1.0f / NN);
        float var = g_stats[2 * 128 + 64 + f] * (1.0f / NN) - mu * mu;
        float v = (ga[node * 64 + f] - mu) * rsqrtf(var + BN_EPS) * gamma[f] + beta[f];
        total += fmaxf(v, 0.0f) * Wf[f];
    }
#pragma unroll
    for (int off = 16; off > 0; off >>= 1)
        total += __shfl_down_sync(0xffffffffu, total, off);
    if (lane == 0) out[node] = total + bf[0];
}

// ---------------- launch ----------------------------------------------------
extern "C" void kernel_launch(void* const* d_in, const int* in_sizes, int n_in,
                              void* d_out, int out_size) {
    const float* x       = (const float*)d_in[0];
    const int*   lab     = (const int*)d_in[1];
    const int*   ei      = (const int*)d_in[2];
    const float* emb     = (const float*)d_in[3];
    const float* W1_0    = (const float*)d_in[4];
    const float* b1_0    = (const float*)d_in[5];
    const float* W2_0    = (const float*)d_in[6];
    const float* b2_0    = (const float*)d_in[7];
    const float* eps_0   = (const float*)d_in[8];
    const float* gamma_0 = (const float*)d_in[9];
    const float* beta_0  = (const float*)d_in[10];
    const float* W1_s    = (const float*)d_in[11];
    const float* b1_s    = (const float*)d_in[12];
    const float* W2_s    = (const float*)d_in[13];
    const float* b2_s    = (const float*)d_in[14];
    const float* eps_s   = (const float*)d_in[15];
    const float* gamma_s = (const float*)d_in[16];
    const float* beta_s  = (const float*)d_in[17];
    const float* Wf      = (const float*)d_in[18];
    const float* bf      = (const float*)d_in[19];
    float* out = (float*)d_out;

    const int*  srcp = ei;
    const int*  dstp = ei + NE;
    const int4* dst4 = (const int4*)(ei + NE);

    // launch 0: embed-pack + zero stats/blocksums + histogram (deg pre-zeroed)
    k_embedhist<<<NE / 4 / 256, 256>>>(x, lab, dst4);
    // launch 1: single-pass scan (+ deferred deg zero)
    k_scanAC<<<NSCAN, 1024>>>();
    // launch 2: scatter (index only)
    k_scatter<<<(NE + 255) / 256, 256>>>(srcp, dstp);
    // launch 3 (profiled): fused layer-0 agg + MLP (no smem weights)
    k_aggmlp0e<<<NN / 32, 256>>>(W1_0, b1_0, W2_0, b2_0, eps_0, emb);

    // layer 1: BN(l0) -> fp16, fused agg+MLP
    k_bnapply<<<(NN * 32 + 255) / 256, 256>>>(0, gamma_0, beta_0);
    k_aggmlp<<<NN / 32, 256>>>(W1_s + 0 * 4096, b1_s + 0 * 64,
                               W2_s + 0 * 4096, b2_s + 0 * 64, eps_s + 0, 1);

    // layer 2: BN(l1) -> fp16, fused agg+MLP
    k_bnapply<<<(NN * 32 + 255) / 256, 256>>>(1, gamma_s + 0 * 64, beta_s + 0 * 64);
    k_aggmlp<<<NN / 32, 256>>>(W1_s + 1 * 4096, b1_s + 1 * 64,
                               W2_s + 1 * 4096, b2_s + 1 * 64, eps_s + 1, 2);

    // final head (BN of layer 2 fused)
    k_final<<<NN / 8, 256>>>(gamma_s + 1 * 64, beta_s + 1 * 64, Wf, bf, out);
}

// round 17
// speedup vs baseline: 1.1996x; 1.0087x over previous
#include <cuda_runtime.h>
#include <cuda_fp16.h>

#define NN 100000
#define NE 3200000
#define BN_EPS 1e-5f
#define NSCAN 98   // ceil((NN+1)/1024)
#define SCAN_FLAG 0x40000000

// ---------------- scratch (static device buffers) ---------------------------
__device__ float4 g_p0[NN];         // packed layer-0 record {x0, x1, label, 0}
__device__ float4 g_a[NN * 16];     // MLP output pre-BN (post relu2) [N,64] fp32
__device__ __half g_ah[NN * 64];    // post-BN+ReLU activations, fp16
__device__ int   g_deg[NN];         // zeroed at end of scanAC (deferred, deterministic)
__device__ int   g_rowstart[NN + 1];
__device__ int   g_cursor[NN];
__device__ int   g_src_sorted[NE];
__device__ int   g_blocksums[NSCAN];
__device__ float g_stats[3 * 128];  // per layer: [0..63]=sum, [64..127]=sumsq

__device__ __forceinline__ float bnr(float v, float sc, float sh) {
    return fmaxf(fmaf(v, sc, sh), 0.0f);
}

// ---------------- packed f32x2 helpers (Blackwell FFMA2 path) ---------------
__device__ __forceinline__ unsigned long long packf2(float a, float b) {
    unsigned long long r;
    asm("mov.b64 %0, {%1, %2};" : "=l"(r) : "f"(a), "f"(b));
    return r;
}
__device__ __forceinline__ unsigned long long fma2(unsigned long long a,
                                                   unsigned long long b,
                                                   unsigned long long c) {
    unsigned long long d;
    asm("fma.rn.f32x2 %0, %1, %2, %3;" : "=l"(d) : "l"(a), "l"(b), "l"(c));
    return d;
}
__device__ __forceinline__ float2 unpackf2(unsigned long long v) {
    float2 r;
    asm("mov.b64 {%0, %1}, %2;" : "=f"(r.x), "=f"(r.y) : "l"(v));
    return r;
}

// ---------------- launch 0: embed-pack + zero stats/blocksums + histogram ---
// g_deg arrives already zeroed (module init on call 1; scanAC re-zeroes after).
__global__ void k_embedhist(const float* __restrict__ x, const int* __restrict__ lab,
                            const int4* __restrict__ dst4) {
    int n = blockIdx.x * blockDim.x + threadIdx.x;
    if (n < 3 * 128) g_stats[n] = 0.0f;
    if (n < NSCAN) g_blocksums[n] = 0;
    if (n < NN) {
        g_p0[n] = make_float4(x[2 * n], x[2 * n + 1],
                              __int_as_float(lab[n]), 0.0f);
    }
    if (n < NE / 4) {
        int4 d = dst4[n];
        atomicAdd(&g_deg[d.x], 1);
        atomicAdd(&g_deg[d.y], 1);
        atomicAdd(&g_deg[d.z], 1);
        atomicAdd(&g_deg[d.w], 1);
    }
}

// ---------------- launch 1: single-kernel scan (parallel lookback) ----------
__global__ void k_scanAC() {
    __shared__ int sm[1024];
    __shared__ int boff;
    int t = threadIdx.x;
    int b = blockIdx.x;
    int i = b * 1024 + t;
    int v = (i < NN) ? g_deg[i] : 0;
    sm[t] = v;
    if (t == 0) boff = 0;
    __syncthreads();
    for (int off = 1; off < 1024; off <<= 1) {
        int add = (t >= off) ? sm[t - off] : 0;
        __syncthreads();
        sm[t] += add;
        __syncthreads();
    }
    if (t == 1023) atomicExch(&g_blocksums[b], sm[1023] | SCAN_FLAG);
    if (t < b) {
        int val;
        do { val = atomicAdd(&g_blocksums[t], 0); } while (!(val & SCAN_FLAG));
        atomicAdd(&boff, val & ~SCAN_FLAG);
    }
    __syncthreads();
    int excl = boff + sm[t] - v;
    if (i <= NN) g_rowstart[i] = excl;
    if (i < NN) {
        g_cursor[i] = excl;
        g_deg[i] = 0;           // deferred zero for next call's histogram
    }
}

// ---------------- launch 2: scatter (counting-sort placement) ---------------
__global__ void k_scatter(const int* __restrict__ src, const int* __restrict__ dst) {
    int e = blockIdx.x * blockDim.x + threadIdx.x;
    if (e >= NE) return;
    int p = atomicAdd(&g_cursor[dst[e]], 1);
    g_src_sorted[p] = src[e];
}

// ---------------- launch 3 (PROFILED): fused layer-0 agg + MLP --------------
// Phase A: 8 thr/node; 4 records in flight (MLP=4, front-batched LDGs) into a
//          SINGLE accumulator bank (reg-neutral vs 2-chain/2-iter form).
//          For deg=32 the whole per-thread workload is one batch.
// Phase B: FFMA2 MLP (DIN=10), weights straight from gmem (L1-resident).
#define SPN 89   // sP node stride (floats): odd vs 32 banks -> conflict-free reduce
#define EMS 12   // semb row stride in floats (48 B)
__device__ __forceinline__ void acc_rec(float* p, float4 r, const float* semb) {
    p[0] += r.x; p[1] += r.y;
    const float4* eb = (const float4*)&semb[__float_as_int(r.z) * EMS];
    float4 e0 = eb[0], e1 = eb[1];
    p[2] += e0.x; p[3] += e0.y; p[4] += e0.z; p[5] += e0.w;
    p[6] += e1.x; p[7] += e1.y; p[8] += e1.z; p[9] += e1.w;
}

__global__ void __launch_bounds__(256) k_aggmlp0e(const float* __restrict__ W1,
                                                  const float* __restrict__ b1,
                                                  const float* __restrict__ W2,
                                                  const float* __restrict__ b2,
                                                  const float* __restrict__ eps_ptr,
                                                  const float* __restrict__ emb) {
    __shared__ __align__(16) float semb[32 * EMS];
    __shared__ float sP[32 * SPN];
    __shared__ float sA[10 * 36];
    __shared__ float sB[64 * 36];
    __shared__ float sred[256];
    __shared__ float qred[256];

    int t = threadIdx.x;
    int node0 = blockIdx.x * 32;

    for (int i = t; i < 32 * EMS; i += 256) {
        int c = i / EMS, d = i % EMS;
        semb[i] = (d < 8) ? emb[c * 8 + d] : 0.0f;
    }
    __syncthreads();

    // ---- Phase A: gather (8 thr/node, 4 records in flight) ----
    {
        int nloc = t >> 3;
        int sub = t & 7;
        int node = node0 + nloc;
        int s = g_rowstart[node], e = g_rowstart[node + 1];
        float p[10];
#pragma unroll
        for (int k = 0; k < 10; k++) p[k] = 0.0f;
        int j = s + sub;
        // main batch: 4 strided records in flight (covers deg<=32 in one shot)
        for (; j + 24 < e; j += 32) {
            int i0 = g_src_sorted[j];
            int i1 = g_src_sorted[j + 8];
            int i2 = g_src_sorted[j + 16];
            int i3 = g_src_sorted[j + 24];
            float4 r0 = g_p0[i0];
            float4 r1 = g_p0[i1];
            float4 r2 = g_p0[i2];
            float4 r3 = g_p0[i3];
            acc_rec(p, r0, semb);
            acc_rec(p, r1, semb);
            acc_rec(p, r2, semb);
            acc_rec(p, r3, semb);
        }
        // remainder: one record at a time
        for (; j < e; j += 8) {
            float4 r = g_p0[g_src_sorted[j]];
            acc_rec(p, r, semb);
        }
        float* myP = &sP[nloc * SPN + sub * 10];
#pragma unroll
        for (int k = 0; k < 10; k++) myP[k] = p[k];
    }
    __syncthreads();

    // ---- reduce 8 sub-partials -> sA[k][n], add (1+eps)*self ----
    {
        float c = 1.0f + *eps_ptr;
        for (int i = t; i < 320; i += 256) {
            int n = i & 31;
            int k = i >> 5;
            float ssum = 0.0f;
#pragma unroll
            for (int sub = 0; sub < 8; sub++) ssum += sP[n * SPN + sub * 10 + k];
            float4 rec = g_p0[node0 + n];
            float hk;
            if (k == 0)      hk = rec.x;
            else if (k == 1) hk = rec.y;
            else             hk = semb[__float_as_int(rec.z) * EMS + (k - 2)];
            sA[k * 36 + n] = fmaf(c, hk, ssum);
        }
    }
    __syncthreads();

    // ---- Phase B: 2-layer MLP (FFMA2, DIN=10, weights from gmem) ----
    int f = t & 63;
    int g = t >> 6;

    unsigned long long a01, a23, a45, a67;
    {
        float bb = b1[f];
        unsigned long long bp = packf2(bb, bb);
        a01 = bp; a23 = bp; a45 = bp; a67 = bp;
    }
#pragma unroll
    for (int k = 0; k < 10; k++) {
        float w = __ldg(&W1[k * 64 + f]);
        unsigned long long ww = packf2(w, w);
        ulonglong2 p0 = *(const ulonglong2*)&sA[k * 36 + g * 8];
        ulonglong2 p1 = *(const ulonglong2*)&sA[k * 36 + g * 8 + 4];
        a01 = fma2(p0.x, ww, a01); a23 = fma2(p0.y, ww, a23);
        a45 = fma2(p1.x, ww, a45); a67 = fma2(p1.y, ww, a67);
    }
    {
        float2 v0 = unpackf2(a01), v1 = unpackf2(a23);
        float2 v2 = unpackf2(a45), v3 = unpackf2(a67);
        float4 y0 = make_float4(fmaxf(v0.x, 0.0f), fmaxf(v0.y, 0.0f),
                                fmaxf(v1.x, 0.0f), fmaxf(v1.y, 0.0f));
        float4 y1 = make_float4(fmaxf(v2.x, 0.0f), fmaxf(v2.y, 0.0f),
                                fmaxf(v3.x, 0.0f), fmaxf(v3.y, 0.0f));
        *(float4*)&sB[f * 36 + g * 8]     = y0;
        *(float4*)&sB[f * 36 + g * 8 + 4] = y1;
    }
    __syncthreads();

    {
        float bb = b2[f];
        unsigned long long bp = packf2(bb, bb);
        a01 = bp; a23 = bp; a45 = bp; a67 = bp;
    }
#pragma unroll
    for (int k = 0; k < 64; k++) {
        float w = __ldg(&W2[k * 64 + f]);
        unsigned long long ww = packf2(w, w);
        ulonglong2 p0 = *(const ulonglong2*)&sB[k * 36 + g * 8];
        ulonglong2 p1 = *(const ulonglong2*)&sB[k * 36 + g * 8 + 4];
        a01 = fma2(p0.x, ww, a01); a23 = fma2(p0.y, ww, a23);
        a45 = fma2(p1.x, ww, a45); a67 = fma2(p1.y, ww, a67);
    }

    float out8[8];
    {
        float2 v0 = unpackf2(a01), v1 = unpackf2(a23);
        float2 v2 = unpackf2(a45), v3 = unpackf2(a67);
        out8[0] = v0.x; out8[1] = v0.y; out8[2] = v1.x; out8[3] = v1.y;
        out8[4] = v2.x; out8[5] = v2.y; out8[6] = v3.x; out8[7] = v3.y;
    }

    float s = 0.0f, qq = 0.0f;
    float* ga = (float*)g_a;
#pragma unroll
    for (int i = 0; i < 8; i++) {
        float v = fmaxf(out8[i], 0.0f);
        ga[(node0 + g * 8 + i) * 64 + f] = v;
        s += v;
        qq += v * v;
    }
    sred[f * 4 + g] = s;
    qred[f * 4 + g] = qq;
    __syncthreads();
    if (t < 64) {
        float ss = sred[t * 4] + sred[t * 4 + 1] + sred[t * 4 + 2] + sred[t * 4 + 3];
        float q2 = qred[t * 4] + qred[t * 4 + 1] + qred[t * 4 + 2] + qred[t * 4 + 3];
        atomicAdd(&g_stats[0 * 128 + t], ss);
        atomicAdd(&g_stats[0 * 128 + 64 + t], q2);
    }
}
#undef SPN
#undef EMS

// ---------------- BN apply + ReLU -> fp16: g_a (fp32) -> g_ah (half) --------
__global__ void __launch_bounds__(256) k_bnapply(int lidx,
                                                 const float* __restrict__ gamma,
                                                 const float* __restrict__ beta) {
    __shared__ float ssc[64], ssh[64];
    int t = threadIdx.x;
    if (t < 64) {
        float mu = g_stats[lidx * 128 + t] * (1.0f / NN);
        float var = g_stats[lidx * 128 + 64 + t] * (1.0f / NN) - mu * mu;
        float r = rsqrtf(var + BN_EPS) * gamma[t];
        ssc[t] = r;
        ssh[t] = beta[t] - mu * r;
    }
    __syncthreads();
    int p = blockIdx.x * 256 + t;              // pair index, NN*32 total
    if (p >= NN * 32) return;
    int f2 = p & 31;
    float2 v = ((const float2*)g_a)[p];
    float y0 = bnr(v.x, ssc[2 * f2], ssh[2 * f2]);
    float y1 = bnr(v.y, ssc[2 * f2 + 1], ssh[2 * f2 + 1]);
    ((__half2*)g_ah)[p] = __floats2half2_rn(y0, y1);
}

// per-value fp32 accumulate (R9 arithmetic — precision-frozen)
__device__ __forceinline__ void accum8(float* a, uint4 v) {
    const __half2* h = (const __half2*)&v;
#pragma unroll
    for (int i = 0; i < 4; i++) {
        float2 f = __half22float2(h[i]);
        a[2 * i]     += f.x;
        a[2 * i + 1] += f.y;
    }
}

// ---------------- FUSED layers 1,2: fp16 gather agg + 2-layer MLP -----------
// Weights read directly from gmem -> 11 KB smem -> high occupancy (R16 form).
__global__ void __launch_bounds__(256) k_aggmlp(const float* __restrict__ W1,
                                                const float* __restrict__ b1,
                                                const float* __restrict__ W2,
                                                const float* __restrict__ b2,
                                                const float* __restrict__ eps_ptr,
                                                int lidx) {
    __shared__ float sAB[64 * 36];
    __shared__ float sred[256];
    __shared__ float qred[256];

    int t = threadIdx.x;
    int node0 = blockIdx.x * 32;

    // ---- Phase A: aggregation (8 thr/node, scalar idx, R9 exact) ----
    {
        int nloc = t >> 3;
        int q = t & 7;
        int node = node0 + nloc;
        const uint4* A = (const uint4*)g_ah;
        int s = g_rowstart[node], e = g_rowstart[node + 1];
        float a0[8] = {0, 0, 0, 0, 0, 0, 0, 0};
        float a1[8] = {0, 0, 0, 0, 0, 0, 0, 0};
        int j = s;
        for (; j + 3 < e; j += 4) {
            int s0 = g_src_sorted[j],     s1 = g_src_sorted[j + 1];
            int s2 = g_src_sorted[j + 2], s3 = g_src_sorted[j + 3];
            uint4 v0 = A[s0 * 8 + q], v1 = A[s1 * 8 + q];
            uint4 v2 = A[s2 * 8 + q], v3 = A[s3 * 8 + q];
            accum8(a0, v0); accum8(a1, v1); accum8(a0, v2); accum8(a1, v3);
        }
        for (; j < e; j++) accum8(a0, A[g_src_sorted[j] * 8 + q]);

        float c = 1.0f + *eps_ptr;
        uint4 w = A[node * 8 + q];
        const __half2* h = (const __half2*)&w;
#pragma unroll
        for (int i = 0; i < 4; i++) {
            float2 f = __half22float2(h[i]);
            float r0 = fmaf(c, f.x, a0[2 * i]     + a1[2 * i]);
            float r1 = fmaf(c, f.y, a0[2 * i + 1] + a1[2 * i + 1]);
            sAB[(q * 8 + 2 * i)     * 36 + nloc] = r0;
            sAB[(q * 8 + 2 * i + 1) * 36 + nloc] = r1;
        }
    }
    __syncthreads();

    // ---- Phase B: 2-layer MLP (FFMA2, weights from gmem) ----
    int f = t & 63;
    int g = t >> 6;

    unsigned long long a01, a23, a45, a67;
    {
        float bb = b1[f];
        unsigned long long bp = packf2(bb, bb);
        a01 = bp; a23 = bp; a45 = bp; a67 = bp;
    }
#pragma unroll
    for (int k = 0; k < 64; k++) {
        float w = __ldg(&W1[k * 64 + f]);
        unsigned long long ww = packf2(w, w);
        ulonglong2 p0 = *(const ulonglong2*)&sAB[k * 36 + g * 8];
        ulonglong2 p1 = *(const ulonglong2*)&sAB[k * 36 + g * 8 + 4];
        a01 = fma2(p0.x, ww, a01); a23 = fma2(p0.y, ww, a23);
        a45 = fma2(p1.x, ww, a45); a67 = fma2(p1.y, ww, a67);
    }
    __syncthreads();
    {
        float2 v0 = unpackf2(a01), v1 = unpackf2(a23);
        float2 v2 = unpackf2(a45), v3 = unpackf2(a67);
        float4 y0 = make_float4(fmaxf(v0.x, 0.0f), fmaxf(v0.y, 0.0f),
                                fmaxf(v1.x, 0.0f), fmaxf(v1.y, 0.0f));
        float4 y1 = make_float4(fmaxf(v2.x, 0.0f), fmaxf(v2.y, 0.0f),
                                fmaxf(v3.x, 0.0f), fmaxf(v3.y, 0.0f));
        *(float4*)&sAB[f * 36 + g * 8]     = y0;
        *(float4*)&sAB[f * 36 + g * 8 + 4] = y1;
    }
    __syncthreads();

    {
        float bb = b2[f];
        unsigned long long bp = packf2(bb, bb);
        a01 = bp; a23 = bp; a45 = bp; a67 = bp;
    }
#pragma unroll
    for (int k = 0; k < 64; k++) {
        float w = __ldg(&W2[k * 64 + f]);
        unsigned long long ww = packf2(w, w);
        ulonglong2 p0 = *(const ulonglong2*)&sAB[k * 36 + g * 8];
        ulonglong2 p1 = *(const ulonglong2*)&sAB[k * 36 + g * 8 + 4];
        a01 = fma2(p0.x, ww, a01); a23 = fma2(p0.y, ww, a23);
        a45 = fma2(p1.x, ww, a45); a67 = fma2(p1.y, ww, a67);
    }

    float out8[8];
    {
        float2 v0 = unpackf2(a01), v1 = unpackf2(a23);
        float2 v2 = unpackf2(a45), v3 = unpackf2(a67);
        out8[0] = v0.x; out8[1] = v0.y; out8[2] = v1.x; out8[3] = v1.y;
        out8[4] = v2.x; out8[5] = v2.y; out8[6] = v3.x; out8[7] = v3.y;
    }

    float s = 0.0f, qq = 0.0f;
    float* ga = (float*)g_a;
#pragma unroll
    for (int i = 0; i < 8; i++) {
        float v = fmaxf(out8[i], 0.0f);
        ga[(node0 + g * 8 + i) * 64 + f] = v;
        s += v;
        qq += v * v;
    }
    sred[f * 4 + g] = s;
    qred[f * 4 + g] = qq;
    __syncthreads();
    if (t < 64) {
        float ss = sred[t * 4] + sred[t * 4 + 1] + sred[t * 4 + 2] + sred[t * 4 + 3];
        float q2 = qred[t * 4] + qred[t * 4 + 1] + qred[t * 4 + 2] + qred[t * 4 + 3];
        atomicAdd(&g_stats[lidx * 128 + t], ss);
        atomicAdd(&g_stats[lidx * 128 + 64 + t], q2);
    }
}

// ---------------- final: BN(layer2) + relu + linear head --------------------
__global__ void k_final(const float* __restrict__ gamma, const float* __restrict__ beta,
                        const float* __restrict__ Wf, const float* __restrict__ bf,
                        float* __restrict__ out) {
    int t = threadIdx.x;
    int lane = t & 31;
    int node = blockIdx.x * 8 + (t >> 5);
    const float* ga = (const float*)g_a;
    float total = 0.0f;
#pragma unroll
    for (int half = 0; half < 2; half++) {
        int f = lane + 32 * half;
        float mu = g_stats[2 * 128 + f] * (1.0f / NN);
        float var = g_stats[2 * 128 + 64 + f] * (1.0f / NN) - mu * mu;
        float v = (ga[node * 64 + f] - mu) * rsqrtf(var + BN_EPS) * gamma[f] + beta[f];
        total += fmaxf(v, 0.0f) * Wf[f];
    }
#pragma unroll
    for (int off = 16; off > 0; off >>= 1)
        total += __shfl_down_sync(0xffffffffu, total, off);
    if (lane == 0) out[node] = total + bf[0];
}

// ---------------- launch ----------------------------------------------------
extern "C" void kernel_launch(void* const* d_in, const int* in_sizes, int n_in,
                              void* d_out, int out_size) {
    const float* x       = (const float*)d_in[0];
    const int*   lab     = (const int*)d_in[1];
    const int*   ei      = (const int*)d_in[2];
    const float* emb     = (const float*)d_in[3];
    const float* W1_0    = (const float*)d_in[4];
    const float* b1_0    = (const float*)d_in[5];
    const float* W2_0    = (const float*)d_in[6];
    const float* b2_0    = (const float*)d_in[7];
    const float* eps_0   = (const float*)d_in[8];
    const float* gamma_0 = (const float*)d_in[9];
    const float* beta_0  = (const float*)d_in[10];
    const float* W1_s    = (const float*)d_in[11];
    const float* b1_s    = (const float*)d_in[12];
    const float* W2_s    = (const float*)d_in[13];
    const float* b2_s    = (const float*)d_in[14];
    const float* eps_s   = (const float*)d_in[15];
    const float* gamma_s = (const float*)d_in[16];
    const float* beta_s  = (const float*)d_in[17];
    const float* Wf      = (const float*)d_in[18];
    const float* bf      = (const float*)d_in[19];
    float* out = (float*)d_out;

    const int*  srcp = ei;
    const int*  dstp = ei + NE;
    const int4* dst4 = (const int4*)(ei + NE);

    // launch 0: embed-pack + zero stats/blocksums + histogram (deg pre-zeroed)
    k_embedhist<<<NE / 4 / 256, 256>>>(x, lab, dst4);
    // launch 1: single-pass scan (+ deferred deg zero)
    k_scanAC<<<NSCAN, 1024>>>();
    // launch 2: scatter (index only)
    k_scatter<<<(NE + 255) / 256, 256>>>(srcp, dstp);
    // launch 3 (profiled): fused layer-0 agg + MLP (4-record MLP gather)
    k_aggmlp0e<<<NN / 32, 256>>>(W1_0, b1_0, W2_0, b2_0, eps_0, emb);

    // layer 1: BN(l0) -> fp16, fused agg+MLP
    k_bnapply<<<(NN * 32 + 255) / 256, 256>>>(0, gamma_0, beta_0);
    k_aggmlp<<<NN / 32, 256>>>(W1_s + 0 * 4096, b1_s + 0 * 64,
                               W2_s + 0 * 4096, b2_s + 0 * 64, eps_s + 0, 1);

    // layer 2: BN(l1) -> fp16, fused agg+MLP
    k_bnapply<<<(NN * 32 + 255) / 256, 256>>>(1, gamma_s + 0 * 64, beta_s + 0 * 64);
    k_aggmlp<<<NN / 32, 256>>>(W1_s + 1 * 4096, b1_s + 1 * 64,
                               W2_s + 1 * 4096, b2_s + 1 * 64, eps_s + 1, 2);

    // final head (BN of layer 2 fused)
    k_final<<<NN / 8, 256>>>(gamma_s + 1 * 64, beta_s + 1 * 64, Wf, bf, out);
}